// round 10
// baseline (speedup 1.0000x reference)
#include <cuda_runtime.h>
#include <math.h>

#define T_LEN 4096
#define NB 2
#define DIM 512
#define CD 14
#define CS 16384
#define NTOK (NB * T_LEN)   // 8192
#define WSTRIDE 20          // padded per-channel stride in smem (16B-aligned slices)

// ---------------- scratch (zero-initialized at module load; k_out's reduction
// blocks reset everything they consume, so graph replays start clean) --------
__device__ float  g_avg_prob[CS];
__device__ int    g_occ[CS];
__device__ int    g_idx[NTOK];
__device__ double g_ent;
__device__ double g_commit;
__device__ double g_cbe;
__device__ int    g_occn;
__device__ int    g_ctr;

// ---------------- K1: fused in-projection + per-token stats ----------------
// Grid: 256 blocks x 512 threads. Each block: 32 tokens, 16 c-groups of 32 channels.
#define TPB 32
#define CG  16
#define CPT (DIM / CG)       // 32
#define NTHR (TPB * CG)      // 512

__global__ __launch_bounds__(NTHR, 2) void k_main(
    const float* __restrict__ z_e,   // (B, DIM, T)
    const float* __restrict__ W_in,  // (CD, DIM)
    const float* __restrict__ b_in)  // (CD,)
{
    // One 40KB buffer, time-multiplexed:
    //   phase A: Ws   = buf[0 .. 512*20)        W_in padded [c*20 + d]
    //   phase B: part = buf[0 .. CG*TPB*CD)     per c-group partials (7168 floats)
    //            xs   = buf[7232 .. 7232+448)   reduced x per token
    __shared__ __align__(16) float buf[DIM * WSTRIDE];
    float* Ws   = buf;
    float* part = buf;
    float* xs   = buf + 7232;

    const int tid = threadIdx.x;

    // float4-wide coalesced LDG over W_in, scattered STS into padded layout
    {
        const float4* w4 = reinterpret_cast<const float4*>(W_in);
        for (int j = tid; j < (CD * DIM) / 4; j += NTHR) {
            float4 v = w4[j];
            int lin = j << 2;
            int d = lin >> 9;            // dim row
            int c = lin & (DIM - 1);     // channel col (multiple of 4)
            Ws[(c + 0) * WSTRIDE + d] = v.x;
            Ws[(c + 1) * WSTRIDE + d] = v.y;
            Ws[(c + 2) * WSTRIDE + d] = v.z;
            Ws[(c + 3) * WSTRIDE + d] = v.w;
        }
    }
    __syncthreads();

    const int u = tid & 31;          // token lane
    const int g = tid >> 5;          // c-group
    const int tok0 = blockIdx.x * TPB;
    const int b = tok0 >> 12;
    const int tbase = tok0 & (T_LEN - 1);
    const float* zp = z_e + (size_t)b * DIM * T_LEN + tbase + u;

    float acc[CD];
#pragma unroll
    for (int d = 0; d < CD; d++) acc[d] = 0.0f;

    const int c0 = g * CPT;
#pragma unroll
    for (int grp = 0; grp < 4; grp++) {
        // front-batch 8 independent LDGs (MLP 8)
        float zb[8];
#pragma unroll
        for (int k = 0; k < 8; k++)
            zb[k] = __ldg(zp + (size_t)(c0 + grp * 8 + k) * T_LEN);
#pragma unroll
        for (int k = 0; k < 8; k++) {
            const int c = c0 + grp * 8 + k;
            const float z = zb[k];
            const float* wp = &Ws[c * WSTRIDE];
            float4 wa = *reinterpret_cast<const float4*>(wp + 0);
            float4 wb = *reinterpret_cast<const float4*>(wp + 4);
            float4 wc = *reinterpret_cast<const float4*>(wp + 8);
            float2 wd = *reinterpret_cast<const float2*>(wp + 12);
            acc[0]  += z * wa.x;  acc[1]  += z * wa.y;  acc[2]  += z * wa.z;  acc[3]  += z * wa.w;
            acc[4]  += z * wb.x;  acc[5]  += z * wb.y;  acc[6]  += z * wb.z;  acc[7]  += z * wb.w;
            acc[8]  += z * wc.x;  acc[9]  += z * wc.y;  acc[10] += z * wc.z;  acc[11] += z * wc.w;
            acc[12] += z * wd.x;  acc[13] += z * wd.y;
        }
    }
    __syncthreads();   // Ws dead; buffer reused as part/xs

    {
        float* pr = &part[(g * TPB + u) * CD];
#pragma unroll
        for (int d = 0; d < CD; d++) pr[d] = acc[d];
    }
    __syncthreads();

    for (int i = tid; i < TPB * CD; i += NTHR) {
        float s = 0.0f;
#pragma unroll
        for (int gg = 0; gg < CG; gg++) s += part[gg * TPB * CD + i];
        xs[i] = s + __ldg(&b_in[i % CD]);
    }
    __syncthreads();

    // warp 0: per-token stats (token = tok0 + tid)
    if (tid < TPB) {
        const int tok = tok0 + tid;
        float x[CD];
#pragma unroll
        for (int d = 0; d < CD; d++) x[d] = xs[tid * CD + d];

        int idx = 0;
#pragma unroll
        for (int d = 0; d < CD; d++)
            if (x[d] > 0.0f) idx |= (1 << (13 - d));
        g_idx[tok] = idx;
        g_occ[idx] = 1;

        float cm = 0.0f;
#pragma unroll
        for (int d = 0; d < CD; d++) {
            float s = (x[d] > 0.0f) ? 1.0f : -1.0f;
            float df = x[d] - s;
            cm += df * df;
        }

        // factorized per-sample entropy; soft dims cached in <=4 scalars
        float ent = 0.0f;
        float p0 = 1.0f;
        float e0 = 0.f, e1 = 0.f, e2 = 0.f, e3 = 0.f;
        int   s0 = 0, s1 = 0, s2 = 0, s3 = 0;
        int m = 0;
#pragma unroll
        for (int d = 0; d < CD; d++) {
            float t = 400.0f * fabsf(x[d]);
            float e = __expf(-t);                    // q/(1-q)
            float inv = 1.0f / (1.0f + e);
            p0 *= inv;
            ent += __logf(1.0f + e) + t * e * inv;   // stable Bernoulli entropy
            if (e >= 1e-8f) {
                int bit = 1 << (13 - d);
                if      (m == 0) { e0 = e; s0 = bit; }
                else if (m == 1) { e1 = e; s1 = bit; }
                else if (m == 2) { e2 = e; s2 = bit; }
                else if (m == 3) { e3 = e; s3 = bit; }
                m++;
            }
        }
        if (m > 4) m = 4;    // P(m>4) ~1e-4/token; dropped mass shifts aux ~3e-5

        const int nsub = 1 << m;
        for (int s = 0; s < nsub; s++) {
            float p = p0;
            int code = idx;
            if (s & 1) { p *= e0; code ^= s0; }
            if (s & 2) { p *= e1; code ^= s1; }
            if (s & 4) { p *= e2; code ^= s2; }
            if (s & 8) { p *= e3; code ^= s3; }
            atomicAdd(&g_avg_prob[code], p);
        }

#pragma unroll
        for (int off = 16; off > 0; off >>= 1) {
            cm  += __shfl_down_sync(0xffffffffu, cm,  off);
            ent += __shfl_down_sync(0xffffffffu, ent, off);
        }
        if (tid == 0) {
            atomicAdd(&g_ent, (double)ent);
            atomicAdd(&g_commit, (double)cm);
        }
    }
}

// ---------------- K2: z_q writeout via split-bit lookup tables ---------------
// Grid 2048 x 512 threads: block = (b, c, half); each thread one independent
// 4-token slab.  lo[m] = sum_{d=7..13} +-W_out[c,d],  hi[h] = sum_{d=0..6}.
// out = b_out[c] + lo[idx & 127] + hi[idx >> 7]
// Blocks 0..63 also reduce the 16384 codebook bins; the last block finalizes
// the scalars and resets all scratch for the next graph replay.
__global__ __launch_bounds__(512) void k_out(
    const float* __restrict__ W_out,  // (DIM, CD)
    const float* __restrict__ b_out,  // (DIM,)
    float* __restrict__ out, int out_size)
{
    __shared__ float tabs[256];       // [0..127]=lo, [128..255]=hi
    __shared__ double sh[256];
    __shared__ int    shc[256];
    __shared__ int    s_last;

    const int tid = threadIdx.x;
    const int bid = blockIdx.x;       // 2048 = b(1) x h(1) x c(9) bits
    const int c = bid & 511;
    const int h = (bid >> 9) & 1;
    const int b = bid >> 10;
    const int t0 = h << 11;           // 2048-token half

    if (tid < 256) {
        const int base = (tid < 128) ? 7 : 0;      // lo: d=7..13, hi: d=0..6
        const int m = tid & 127;
        float s = 0.0f;
#pragma unroll
        for (int d = 0; d < 7; d++) {
            float w = __ldg(&W_out[c * CD + base + d]);
            unsigned sgn = (((unsigned)m >> (6 - d)) & 1u) ? 0u : 0x80000000u;
            s += __int_as_float(__float_as_int(w) ^ sgn);
        }
        tabs[tid] = s;
    }
    const float bc = __ldg(&b_out[c]);
    __syncthreads();

    const int t = t0 + (tid << 2);
    const int4 iv = *reinterpret_cast<const int4*>(&g_idx[b * T_LEN + t]);

    float4 r;
    r.x = bc + tabs[iv.x & 127] + tabs[128 + (iv.x >> 7)];
    r.y = bc + tabs[iv.y & 127] + tabs[128 + (iv.y >> 7)];
    r.z = bc + tabs[iv.z & 127] + tabs[128 + (iv.z >> 7)];
    r.w = bc + tabs[iv.w & 127] + tabs[128 + (iv.w >> 7)];

    float4* op = reinterpret_cast<float4*>(&out[((size_t)(b * DIM + c)) * T_LEN + t]);
    *op = r;

    // ---- codebook entropy + occupancy: 64 blocks x 256 threads cover CS ----
    if (bid < 64) {
        if (tid < 256) {
            const int i = bid * 256 + tid;
            float ap_raw = g_avg_prob[i];
            int   oc     = g_occ[i];
            double v = 0.0;
            if (ap_raw != 0.0f || oc != 0) {
                float ap = ap_raw * (1.0f / NTOK);
                v = (double)(-ap * logf(fmaxf(ap, 1e-20f)));
                g_avg_prob[i] = 0.0f;   // reset for next graph replay
                g_occ[i] = 0;
            }
            sh[tid] = v; shc[tid] = oc;
        }
        __syncthreads();
        for (int s = 128; s > 0; s >>= 1) {
            if (tid < s) { sh[tid] += sh[tid + s]; shc[tid] += shc[tid + s]; }
            __syncthreads();
        }
        if (tid == 0) {
            atomicAdd(&g_cbe, sh[0]);
            atomicAdd(&g_occn, shc[0]);
            __threadfence();
            int prev = atomicAdd(&g_ctr, 1);
            s_last = (prev == 63);
        }
        __syncthreads();
        if (s_last && tid == 0) {
            __threadfence();   // acquire: all 64 blocks' partials visible
            double cbe = *((volatile double*)&g_cbe);
            int    occ = *((volatile int*)&g_occn);
            double ge  = *((volatile double*)&g_ent);
            double gc  = *((volatile double*)&g_commit);
            double pse = ge / (double)NTOK;
            double commit = gc / (double)(NTOK * CD);
            double aux = 0.1 * (pse - cbe) + 0.25 * commit;
            out[out_size - 2] = (float)aux;
            out[out_size - 1] = (float)occ / (float)CS;
            g_cbe = 0.0; g_occn = 0;
            g_ent = 0.0; g_commit = 0.0;
            g_ctr = 0;
        }
    }
}

// ---------------- launch ----------------
extern "C" void kernel_launch(void* const* d_in, const int* in_sizes, int n_in,
                              void* d_out, int out_size) {
    const float* z_e   = (const float*)d_in[0];
    const float* W_in  = (const float*)d_in[1];
    const float* b_in  = (const float*)d_in[2];
    const float* W_out = (const float*)d_in[3];
    const float* b_out = (const float*)d_in[4];
    float* out = (float*)d_out;

    k_main<<<NTOK / TPB, NTHR>>>(z_e, W_in, b_in);
    k_out<<<2048, 512>>>(W_out, b_out, out, out_size);
}

// round 11
// speedup vs baseline: 1.0819x; 1.0819x over previous
#include <cuda_runtime.h>
#include <math.h>

#define T_LEN 4096
#define NB 2
#define DIM 512
#define CD 14
#define CS 16384
#define NTOK (NB * T_LEN)   // 8192
#define WSTRIDE 20          // padded per-channel stride in smem (16B-aligned slices)

// ---------------- scratch (zero-initialized at module load; k_out's reduction
// blocks reset everything they consume, so graph replays start clean) --------
__device__ float  g_avg_prob[CS];
__device__ int    g_occ[CS];
__device__ int    g_idx[NTOK];
__device__ double g_ent;
__device__ double g_commit;
__device__ double g_cbe;
__device__ int    g_occn;
__device__ int    g_ctr;

// tiny no-op kernel: shifts ncu's capture index onto k_main this round
__global__ void k_noop() {}

// ---------------- K1: fused in-projection + per-token stats ----------------
// Grid: 256 blocks x 512 threads. Each block: 32 tokens, 16 c-groups of 32 channels.
#define TPB 32
#define CG  16
#define CPT (DIM / CG)       // 32
#define NTHR (TPB * CG)      // 512

__global__ __launch_bounds__(NTHR, 2) void k_main(
    const float* __restrict__ z_e,   // (B, DIM, T)
    const float* __restrict__ W_in,  // (CD, DIM)
    const float* __restrict__ b_in)  // (CD,)
{
    // One 40KB buffer, time-multiplexed:
    //   phase A: Ws   = buf[0 .. 512*20)        W_in padded [c*20 + d]
    //   phase B: part = buf[0 .. CG*TPB*CD)     per c-group partials (7168 floats)
    //            xs   = buf[7232 .. 7232+448)   reduced x per token
    __shared__ __align__(16) float buf[DIM * WSTRIDE];
    float* Ws   = buf;
    float* part = buf;
    float* xs   = buf + 7232;

    const int tid = threadIdx.x;

    // scalar coalesced LDG over W_in; STS scatter is 4-way conflicted (20c mod 32)
    for (int j = tid; j < CD * DIM; j += NTHR) {
        int d = j >> 9;              // dim row
        int c = j & (DIM - 1);       // channel col
        Ws[c * WSTRIDE + d] = W_in[j];
    }
    __syncthreads();

    const int u = tid & 31;          // token lane
    const int g = tid >> 5;          // c-group
    const int tok0 = blockIdx.x * TPB;
    const int b = tok0 >> 12;
    const int tbase = tok0 & (T_LEN - 1);
    const float* zp = z_e + (size_t)b * DIM * T_LEN + tbase + u;

    float acc[CD];
#pragma unroll
    for (int d = 0; d < CD; d++) acc[d] = 0.0f;

    const int c0 = g * CPT;
#pragma unroll
    for (int grp = 0; grp < 4; grp++) {
        // front-batch 8 independent LDGs (MLP 8)
        float zb[8];
#pragma unroll
        for (int k = 0; k < 8; k++)
            zb[k] = __ldg(zp + (size_t)(c0 + grp * 8 + k) * T_LEN);
#pragma unroll
        for (int k = 0; k < 8; k++) {
            const int c = c0 + grp * 8 + k;
            const float z = zb[k];
            const float* wp = &Ws[c * WSTRIDE];
            float4 wa = *reinterpret_cast<const float4*>(wp + 0);
            float4 wb = *reinterpret_cast<const float4*>(wp + 4);
            float4 wc = *reinterpret_cast<const float4*>(wp + 8);
            float2 wd = *reinterpret_cast<const float2*>(wp + 12);
            acc[0]  += z * wa.x;  acc[1]  += z * wa.y;  acc[2]  += z * wa.z;  acc[3]  += z * wa.w;
            acc[4]  += z * wb.x;  acc[5]  += z * wb.y;  acc[6]  += z * wb.z;  acc[7]  += z * wb.w;
            acc[8]  += z * wc.x;  acc[9]  += z * wc.y;  acc[10] += z * wc.z;  acc[11] += z * wc.w;
            acc[12] += z * wd.x;  acc[13] += z * wd.y;
        }
    }
    __syncthreads();   // Ws dead; buffer reused as part/xs

    {
        float* pr = &part[(g * TPB + u) * CD];
#pragma unroll
        for (int d = 0; d < CD; d++) pr[d] = acc[d];
    }
    __syncthreads();

    for (int i = tid; i < TPB * CD; i += NTHR) {
        float s = 0.0f;
#pragma unroll
        for (int gg = 0; gg < CG; gg++) s += part[gg * TPB * CD + i];
        xs[i] = s + __ldg(&b_in[i % CD]);
    }
    __syncthreads();

    // warp 0: per-token stats (token = tok0 + tid)
    if (tid < TPB) {
        const int tok = tok0 + tid;
        float x[CD];
#pragma unroll
        for (int d = 0; d < CD; d++) x[d] = xs[tid * CD + d];

        int idx = 0;
#pragma unroll
        for (int d = 0; d < CD; d++)
            if (x[d] > 0.0f) idx |= (1 << (13 - d));
        g_idx[tok] = idx;
        g_occ[idx] = 1;

        float cm = 0.0f;
#pragma unroll
        for (int d = 0; d < CD; d++) {
            float s = (x[d] > 0.0f) ? 1.0f : -1.0f;
            float df = x[d] - s;
            cm += df * df;
        }

        // factorized per-sample entropy; soft dims cached in <=4 scalars
        float ent = 0.0f;
        float p0 = 1.0f;
        float e0 = 0.f, e1 = 0.f, e2 = 0.f, e3 = 0.f;
        int   s0 = 0, s1 = 0, s2 = 0, s3 = 0;
        int m = 0;
#pragma unroll
        for (int d = 0; d < CD; d++) {
            float t = 400.0f * fabsf(x[d]);
            float e = __expf(-t);                    // q/(1-q)
            float inv = 1.0f / (1.0f + e);
            p0 *= inv;
            ent += __logf(1.0f + e) + t * e * inv;   // stable Bernoulli entropy
            if (e >= 1e-8f) {
                int bit = 1 << (13 - d);
                if      (m == 0) { e0 = e; s0 = bit; }
                else if (m == 1) { e1 = e; s1 = bit; }
                else if (m == 2) { e2 = e; s2 = bit; }
                else if (m == 3) { e3 = e; s3 = bit; }
                m++;
            }
        }
        if (m > 4) m = 4;    // P(m>4) ~1e-4/token; dropped mass shifts aux ~3e-5

        const int nsub = 1 << m;
        for (int s = 0; s < nsub; s++) {
            float p = p0;
            int code = idx;
            if (s & 1) { p *= e0; code ^= s0; }
            if (s & 2) { p *= e1; code ^= s1; }
            if (s & 4) { p *= e2; code ^= s2; }
            if (s & 8) { p *= e3; code ^= s3; }
            atomicAdd(&g_avg_prob[code], p);
        }

#pragma unroll
        for (int off = 16; off > 0; off >>= 1) {
            cm  += __shfl_down_sync(0xffffffffu, cm,  off);
            ent += __shfl_down_sync(0xffffffffu, ent, off);
        }
        if (tid == 0) {
            atomicAdd(&g_ent, (double)ent);
            atomicAdd(&g_commit, (double)cm);
        }
    }
}

// ---------------- K2: z_q writeout via split-bit lookup tables ---------------
// Per block: one channel c, 1024 tokens (grid 4096). Two 128-entry smem tables:
//   lo[m] = sum_{d=7..13} +-W_out[c,d],  hi[h] = sum_{d=0..6} +-W_out[c,d]
// out = b_out[c] + lo[idx & 127] + hi[idx >> 7]
// Blocks 0..63 also reduce the 16384 codebook bins; the last block finalizes
// the scalars and resets all scratch for the next graph replay.
__global__ __launch_bounds__(256) void k_out(
    const float* __restrict__ W_out,  // (DIM, CD)
    const float* __restrict__ b_out,  // (DIM,)
    float* __restrict__ out, int out_size)
{
    __shared__ float tabs[256];       // [0..127]=lo, [128..255]=hi
    __shared__ double sh[256];
    __shared__ int    shc[256];
    __shared__ int    s_last;

    const int tid = threadIdx.x;
    const int bid = blockIdx.x;       // 4096 blocks = b(1) x q(2) x c(9) bits
    const int c = bid & 511;
    const int q = (bid >> 9) & 3;
    const int b = bid >> 11;
    const int t0 = q << 10;           // 1024-token chunk

    {
        const int base = (tid < 128) ? 7 : 0;      // lo: d=7..13, hi: d=0..6
        const int m = tid & 127;
        float s = 0.0f;
#pragma unroll
        for (int d = 0; d < 7; d++) {
            float w = __ldg(&W_out[c * CD + base + d]);
            unsigned sgn = (((unsigned)m >> (6 - d)) & 1u) ? 0u : 0x80000000u;
            s += __int_as_float(__float_as_int(w) ^ sgn);
        }
        tabs[tid] = s;
    }
    const float bc = __ldg(&b_out[c]);
    __syncthreads();

    const int t = t0 + (tid << 2);
    const int4 iv = *reinterpret_cast<const int4*>(&g_idx[b * T_LEN + t]);

    float4 r;
    r.x = bc + tabs[iv.x & 127] + tabs[128 + (iv.x >> 7)];
    r.y = bc + tabs[iv.y & 127] + tabs[128 + (iv.y >> 7)];
    r.z = bc + tabs[iv.z & 127] + tabs[128 + (iv.z >> 7)];
    r.w = bc + tabs[iv.w & 127] + tabs[128 + (iv.w >> 7)];

    float4* op = reinterpret_cast<float4*>(&out[((size_t)(b * DIM + c)) * T_LEN + t]);
    *op = r;

    // ---- codebook entropy + occupancy: 64 blocks x 256 threads cover CS ----
    if (bid < 64) {
        const int i = bid * 256 + tid;
        float ap_raw = g_avg_prob[i];
        int   oc     = g_occ[i];
        double v = 0.0;
        if (ap_raw != 0.0f || oc != 0) {
            float ap = ap_raw * (1.0f / NTOK);
            v = (double)(-ap * logf(fmaxf(ap, 1e-20f)));
            g_avg_prob[i] = 0.0f;   // reset for next graph replay
            g_occ[i] = 0;
        }
        sh[tid] = v; shc[tid] = oc;
        __syncthreads();
        for (int s = 128; s > 0; s >>= 1) {
            if (tid < s) { sh[tid] += sh[tid + s]; shc[tid] += shc[tid + s]; }
            __syncthreads();
        }
        if (tid == 0) {
            atomicAdd(&g_cbe, sh[0]);
            atomicAdd(&g_occn, shc[0]);
            __threadfence();
            int prev = atomicAdd(&g_ctr, 1);
            s_last = (prev == 63);
        }
        __syncthreads();
        if (s_last && tid == 0) {
            __threadfence();   // acquire: all 64 blocks' partials visible
            double cbe = *((volatile double*)&g_cbe);
            int    occ = *((volatile int*)&g_occn);
            double ge  = *((volatile double*)&g_ent);
            double gc  = *((volatile double*)&g_commit);
            double pse = ge / (double)NTOK;
            double commit = gc / (double)(NTOK * CD);
            double aux = 0.1 * (pse - cbe) + 0.25 * commit;
            out[out_size - 2] = (float)aux;
            out[out_size - 1] = (float)occ / (float)CS;
            g_cbe = 0.0; g_occn = 0;
            g_ent = 0.0; g_commit = 0.0;
            g_ctr = 0;
        }
    }
}

// ---------------- launch ----------------
extern "C" void kernel_launch(void* const* d_in, const int* in_sizes, int n_in,
                              void* d_out, int out_size) {
    const float* z_e   = (const float*)d_in[0];
    const float* W_in  = (const float*)d_in[1];
    const float* b_in  = (const float*)d_in[2];
    const float* W_out = (const float*)d_in[3];
    const float* b_out = (const float*)d_in[4];
    float* out = (float*)d_out;

    k_noop<<<1, 32>>>();   // shifts ncu capture index onto k_main (period-3 sequence)
    k_main<<<NTOK / TPB, NTHR>>>(z_e, W_in, b_in);
    k_out<<<4096, 256>>>(W_out, b_out, out, out_size);
}